// round 1
// baseline (speedup 1.0000x reference)
#include <cuda_runtime.h>
#include <math.h>

// Shapes (fixed by the problem): x,y [4,3,1024,1024] f32; mask_y [4,8,1024,1024] f32.
// Output: 3 f32 scalars (sum_l1, sum_l2, sum_l3).
#define NPIX   4194304        // B*H*W = 4*1024*1024
#define HW4    262144         // (H*W)/4 in float4 units
#define GROUPS 1048576        // NPIX/4
#define NCLS   8
#define OVF_CAP 8192

// ---- device-global accumulators (scratch; no allocations) ----
__device__ double g_Sx[NCLS];
__device__ double g_Sy[NCLS];
__device__ unsigned long long g_cnt[NCLS];
__device__ double g_pow;            // sum over all pixels (both nonzero) of pow(x_avg, y_avg)
__device__ double g_sxx;            // sum over all pixels of x_avg^2
__device__ int    g_ovf_n;          // count of exceptional pixels (x_avg==0 or y_avg==0)
__device__ int    g_ovf_lab[OVF_CAP];
__device__ float  g_ovf_x[OVF_CAP];
__device__ float  g_ovf_y[OVF_CAP];

__global__ void init_kernel() {
    int t = threadIdx.x;
    if (t < NCLS) { g_Sx[t] = 0.0; g_Sy[t] = 0.0; g_cnt[t] = 0ull; }
    if (t == NCLS) { g_pow = 0.0; g_sxx = 0.0; g_ovf_n = 0; }
}

__device__ __forceinline__ float comp4(const float4& v, int j) {
    switch (j) { case 0: return v.x; case 1: return v.y; case 2: return v.z; default: return v.w; }
}

__global__ void __launch_bounds__(256)
main_kernel(const float* __restrict__ xg, const float* __restrict__ yg,
            const float* __restrict__ mg) {
    __shared__ double ssx[NCLS], ssy[NCLS];
    __shared__ double spw, ssq;
    __shared__ unsigned long long scn[NCLS];
    if (threadIdx.x < NCLS) { ssx[threadIdx.x] = 0.0; ssy[threadIdx.x] = 0.0; scn[threadIdx.x] = 0ull; }
    if (threadIdx.x == NCLS) { spw = 0.0; ssq = 0.0; }
    __syncthreads();

    // per-thread register accumulators
    float sx[NCLS], sy[NCLS];
    int   cn[NCLS];
#pragma unroll
    for (int L = 0; L < NCLS; L++) { sx[L] = 0.f; sy[L] = 0.f; cn[L] = 0; }
    float powacc = 0.f, sqacc = 0.f;

    const float4* x4 = (const float4*)xg;
    const float4* y4 = (const float4*)yg;
    const float4* m4 = (const float4*)mg;

    int tid    = blockIdx.x * blockDim.x + threadIdx.x;
    int stride = gridDim.x * blockDim.x;

    for (int g = tid; g < GROUPS; g += stride) {
        int b  = g >> 18;            // g / HW4
        int hw = g & (HW4 - 1);

        // front-batched coalesced float4 loads: 8 mask planes + 3 x planes + 3 y planes
        float4 mv[8];
#pragma unroll
        for (int c = 0; c < 8; c++) mv[c] = m4[(size_t)(b * 8 + c) * HW4 + hw];
        float4 xv[3];
#pragma unroll
        for (int c = 0; c < 3; c++) xv[c] = x4[(size_t)(b * 3 + c) * HW4 + hw];
        float4 yv[3];
#pragma unroll
        for (int c = 0; c < 3; c++) yv[c] = y4[(size_t)(b * 3 + c) * HW4 + hw];

#pragma unroll
        for (int j = 0; j < 4; j++) {
            // argmax over 8 classes, first-occurrence-of-max (strict >)
            float best = comp4(mv[0], j);
            int   bi   = 0;
#pragma unroll
            for (int c = 1; c < 8; c++) {
                float v = comp4(mv[c], j);
                if (v > best) { best = v; bi = c; }
            }
            float xa = ((comp4(xv[0], j) + comp4(xv[1], j)) + comp4(xv[2], j)) * (1.0f / 3.0f);
            float ya = ((comp4(yv[0], j) + comp4(yv[1], j)) + comp4(yv[2], j)) * (1.0f / 3.0f);

            sqacc += xa * xa;   // zeros contribute 0 -> exactly correct for loss3 decomposition

            bool xz = (xa == 0.0f), yz = (ya == 0.0f);
            if (!xz && !yz) {
                powacc += __powf(xa, ya);
            } else {
                // exceptional pixel: needs region-average substitution, resolved in final kernel
                int i = atomicAdd(&g_ovf_n, 1);
                if (i < OVF_CAP) { g_ovf_lab[i] = bi; g_ovf_x[i] = xa; g_ovf_y[i] = ya; }
            }

            // per-label register scatter (predicated by compiler, no atomics)
#pragma unroll
            for (int L = 0; L < NCLS; L++) {
                if (bi == L) { sx[L] += xa; sy[L] += ya; cn[L]++; }
            }
        }
    }

    // warp reduction
    const unsigned full = 0xffffffffu;
#pragma unroll
    for (int L = 0; L < NCLS; L++) {
#pragma unroll
        for (int o = 16; o > 0; o >>= 1) {
            sx[L] += __shfl_down_sync(full, sx[L], o);
            sy[L] += __shfl_down_sync(full, sy[L], o);
            cn[L] += __shfl_down_sync(full, cn[L], o);
        }
    }
#pragma unroll
    for (int o = 16; o > 0; o >>= 1) {
        powacc += __shfl_down_sync(full, powacc, o);
        sqacc  += __shfl_down_sync(full, sqacc, o);
    }

    if ((threadIdx.x & 31) == 0) {
#pragma unroll
        for (int L = 0; L < NCLS; L++) {
            atomicAdd(&ssx[L], (double)sx[L]);
            atomicAdd(&ssy[L], (double)sy[L]);
            atomicAdd(&scn[L], (unsigned long long)cn[L]);
        }
        atomicAdd(&spw, (double)powacc);
        atomicAdd(&ssq, (double)sqacc);
    }
    __syncthreads();

    if (threadIdx.x < NCLS) {
        atomicAdd(&g_Sx[threadIdx.x], ssx[threadIdx.x]);
        atomicAdd(&g_Sy[threadIdx.x], ssy[threadIdx.x]);
        atomicAdd(&g_cnt[threadIdx.x], scn[threadIdx.x]);
    }
    if (threadIdx.x == NCLS) {
        atomicAdd(&g_pow, spw);
        atomicAdd(&g_sxx, ssq);
    }
}

__global__ void final_kernel(float* __restrict__ out) {
    if (threadIdx.x != 0 || blockIdx.x != 0) return;
    const double N = (double)NPIX;

    double xra[NCLS], yra[NCLS];
#pragma unroll
    for (int L = 0; L < NCLS; L++) {
        xra[L] = g_Sx[L] / N;
        yra[L] = g_Sy[L] / N;
    }

    // resolve exceptional (zero-valued) pixels exactly
    int zx[NCLS], zboth[NCLS];
#pragma unroll
    for (int L = 0; L < NCLS; L++) { zx[L] = 0; zboth[L] = 0; }
    double exc = 0.0;
    int nov = g_ovf_n; if (nov > OVF_CAP) nov = OVF_CAP;
    for (int i = 0; i < nov; i++) {
        int   lab = g_ovf_lab[i];
        float xa  = g_ovf_x[i];
        float ya  = g_ovf_y[i];
        bool  xz  = (xa == 0.0f), yz = (ya == 0.0f);
        if (xz) zx[lab]++;
        if (xz && yz)      zboth[lab]++;                    // contributes pow(xra,yra), counted below
        else if (xz)       exc += pow(xra[lab], (double)ya);
        else /* yz */      exc += pow((double)xa, yra[lab]);
    }

    double l1 = 0.0, l2 = 0.0, l3 = 0.0;
#pragma unroll
    for (int L = 0; L < NCLS; L++) {
        double p = pow(xra[L], yra[L]);   // pow(0,0)=1 matches jnp for empty labels
        l2 += p;
        l1 += (N - (double)g_cnt[L] + (double)zboth[L]) * p;
        double cnz = (double)g_cnt[L] - (double)zx[L];
        l3 += 2.0 * xra[L] * g_Sx[L] - cnz * xra[L] * xra[L];
    }
    l1 = (l1 + g_pow + exc) / N;
    l3 = (g_sxx - l3) / N;

    out[0] = (float)l1;
    out[1] = (float)l2;
    out[2] = (float)l3;
}

extern "C" void kernel_launch(void* const* d_in, const int* in_sizes, int n_in,
                              void* d_out, int out_size) {
    const float* x  = (const float*)d_in[0];
    const float* y  = (const float*)d_in[1];
    const float* mk = (const float*)d_in[2];
    float* out = (float*)d_out;

    init_kernel<<<1, 32>>>();
    main_kernel<<<1184, 256>>>(x, y, mk);
    final_kernel<<<1, 32>>>(out);
}